// round 17
// baseline (speedup 1.0000x reference)
#include <cuda_runtime.h>
#include <cuda_bf16.h>
#include <cuda_fp16.h>
#include <cstdint>

// ---------------- problem constants ----------------
#define DI   128
#define BATCH 2
#define HDm  64
#define WDm  96
#define HUm  128
#define WUm  192
#define SDL  (HDm*WDm)           // 6144
#define SPL  (HUm*WUm)           // 24576
#define ND   (BATCH*SDL)         // 12288
#define NP   (BATCH*SPL)         // 49152
#define KVP  640                 // kv0(256) | kv1(256) | ctxp(128)
#define NTILES 26                // 0-20 transformer, 21-25 folded kv/ctxp
#define WTS  17408               // fp16 per weight tile (128 x 136)

typedef unsigned long long u64;

// ---------------- device scratch ----------------
__device__ float g_ctxln[ND*DI];
__device__ float g_x[NP*DI];
__device__ float g_kvp[ND*KVP];
__device__ float g_W[DI*KVP];
__device__ float g_bias[KVP];
__device__ __half g_Whi[NTILES*WTS];   // [k][n] tiles, stride 136

// ---------------- HMMA helpers (plain PTX, sm_80+) ----------------
__device__ __forceinline__ uint32_t smem_u32(const void* p) {
    uint32_t a;
    asm("{ .reg .u64 t; cvta.to.shared.u64 t, %1; cvt.u32.u64 %0, t; }"
        : "=r"(a) : "l"(p));
    return a;
}
__device__ __forceinline__ void ldsm_x4(uint32_t r[4], uint32_t addr) {
    asm volatile("ldmatrix.sync.aligned.m8n8.x4.shared.b16 {%0,%1,%2,%3}, [%4];"
        : "=r"(r[0]), "=r"(r[1]), "=r"(r[2]), "=r"(r[3]) : "r"(addr));
}
__device__ __forceinline__ void ldsm_x4t(uint32_t r[4], uint32_t addr) {
    asm volatile("ldmatrix.sync.aligned.m8n8.x4.trans.shared.b16 {%0,%1,%2,%3}, [%4];"
        : "=r"(r[0]), "=r"(r[1]), "=r"(r[2]), "=r"(r[3]) : "r"(addr));
}
__device__ __forceinline__ void mma16816(float d[4], const uint32_t a[4],
                                         const uint32_t b[2]) {
    asm volatile(
        "mma.sync.aligned.m16n8k16.row.col.f32.f16.f16.f32 "
        "{%0,%1,%2,%3}, {%4,%5,%6,%7}, {%8,%9}, {%0,%1,%2,%3};"
        : "+f"(d[0]), "+f"(d[1]), "+f"(d[2]), "+f"(d[3])
        : "r"(a[0]), "r"(a[1]), "r"(a[2]), "r"(a[3]), "r"(b[0]), "r"(b[1]));
}

// write split-fp16 pair at (r, c..c+1), row stride 272 B (hi+lo, dgemm)
__device__ __forceinline__ void w2a(char* hi, char* lo, int r, int c,
                                    float v0, float v1) {
    __half h0 = __float2half_rn(v0), h1 = __float2half_rn(v1);
    float l0 = v0 - __half2float(h0);
    float l1 = v1 - __half2float(h1);
    __half2 H = __halves2half2(h0, h1);
    __half2 L = __halves2half2(__float2half_rn(l0), __float2half_rn(l1));
    int off = r*272 + c*2;
    *(uint32_t*)(hi + off) = *(uint32_t*)&H;
    *(uint32_t*)(lo + off) = *(uint32_t*)&L;
}
// hi-only variant (mega)
__device__ __forceinline__ void w2a_hi(char* hi, int r, int c,
                                       float v0, float v1) {
    __half2 H = __halves2half2(__float2half_rn(v0), __float2half_rn(v1));
    *(uint32_t*)(hi + r*272 + c*2) = *(uint32_t*)&H;
}

// ---- half-K warp GEMM, split-A 2-term (dgemm) ----
__device__ __forceinline__ void wgemm_half(const char* Ahi, const char* Alo,
                                           const char* Bhi,
                                           float acc[8][4], int mrow, int nh,
                                           int lane, int kh) {
    uint32_t aHi = smem_u32(Ahi), aLo = smem_u32(Alo);
    uint32_t bHi = smem_u32(Bhi);
    int mat = lane >> 3, r8 = lane & 7;
    uint32_t aRow = (uint32_t)((mrow + (mat & 1)*8 + r8) * 272
                               + (mat >> 1) * 16 + kh*128);
    uint32_t bBase = (uint32_t)(((mat & 1)*8 + r8) * 272
                                + (mat >> 1) * 16 + nh*128);
    #pragma unroll
    for (int ks = 0; ks < 4; ks++) {
        uint32_t Ah[4], Al[4];
        ldsm_x4(Ah, aHi + aRow + ks*32);
        ldsm_x4(Al, aLo + aRow + ks*32);
        uint32_t bko = bBase + (uint32_t)(ks*16*272);
        #pragma unroll
        for (int np = 0; np < 4; np++) {
            uint32_t Bh[4];
            ldsm_x4t(Bh, bHi + bko + np*32);
            mma16816(acc[2*np],   Ah, Bh);
            mma16816(acc[2*np],   Al, Bh);
            mma16816(acc[2*np+1], Ah, Bh+2);
            mma16816(acc[2*np+1], Al, Bh+2);
        }
    }
}

// ---- half-K warp GEMM, pure fp16 single-term (mega) ----
__device__ __forceinline__ void wgemm_half1(const char* Ahi, const char* Bhi,
                                            float acc[8][4], int mrow, int nh,
                                            int lane, int kh) {
    uint32_t aHi = smem_u32(Ahi);
    uint32_t bHi = smem_u32(Bhi);
    int mat = lane >> 3, r8 = lane & 7;
    uint32_t aRow = (uint32_t)((mrow + (mat & 1)*8 + r8) * 272
                               + (mat >> 1) * 16 + kh*128);
    uint32_t bBase = (uint32_t)(((mat & 1)*8 + r8) * 272
                                + (mat >> 1) * 16 + nh*128);
    #pragma unroll
    for (int ks = 0; ks < 4; ks++) {
        uint32_t Ah[4];
        ldsm_x4(Ah, aHi + aRow + ks*32);
        uint32_t bko = bBase + (uint32_t)(ks*16*272);
        #pragma unroll
        for (int np = 0; np < 4; np++) {
            uint32_t Bh[4];
            ldsm_x4t(Bh, bHi + bko + np*32);
            mma16816(acc[2*np],   Ah, Bh);
            mma16816(acc[2*np+1], Ah, Bh+2);
        }
    }
}

// ---- register prefetch of one B half (1088 float4), NT = block threads ----
struct PF { float4 h[5]; };

template<int NT>
__device__ __forceinline__ void pf_load(PF& pf, int tile, int kh, int t) {
    const float4* sh = (const float4*)(g_Whi + (size_t)tile*WTS + kh*64*136);
    #pragma unroll
    for (int i = 0; i < (1088 + NT - 1)/NT; i++) {
        int f = t + i*NT;
        if (f < 1088) pf.h[i] = __ldg(sh + f);
    }
}
template<int NT>
__device__ __forceinline__ void pf_store(const PF& pf, char* Bhi, int t) {
    float4* dh = (float4*)Bhi;
    #pragma unroll
    for (int i = 0; i < (1088 + NT - 1)/NT; i++) {
        int f = t + i*NT;
        if (f < 1088) dh[f] = pf.h[i];
    }
}

// pipelined tile, 2-term single buffer (dgemm, unchanged)
__device__ __forceinline__ void gemm_tile_pf(PF& pf,
                                             const char* sAhi, const char* sAlo,
                                             char* sBhi,
                                             float acc[8][4], int tile,
                                             int next_tile,
                                             int mrow, int nh, int lane, int t) {
    pf_store<256>(pf, sBhi, t);
    __syncthreads();
    pf_load<256>(pf, tile, 1, t);
    wgemm_half(sAhi, sAlo, sBhi, acc, mrow, nh, lane, 0);
    __syncthreads();
    pf_store<256>(pf, sBhi, t);
    __syncthreads();
    if (next_tile >= 0) pf_load<256>(pf, next_tile, 0, t);
    wgemm_half(sAhi, sAlo, sBhi, acc, mrow, nh, lane, 1);
    __syncthreads();
}

// double-buffered single-term tile (mega, 512 threads): 2 syncs, no trailing
__device__ __forceinline__ void gemm_tile_db1(PF& pf, const char* sAhi,
                                              char* sB0, char* sB1,
                                              float acc[8][4], int tile,
                                              int next_tile,
                                              int mrow, int nh, int lane, int t) {
    pf_store<512>(pf, sB0, t);
    pf_load<512>(pf, tile, 1, t);
    __syncthreads();                       // sB0 ready
    wgemm_half1(sAhi, sB0, acc, mrow, nh, lane, 0);
    pf_store<512>(pf, sB1, t);
    if (next_tile >= 0) pf_load<512>(pf, next_tile, 0, t);
    __syncthreads();                       // sB1 ready, B0 reads done
    wgemm_half1(sAhi, sB1, acc, mrow, nh, lane, 1);
}

// ========================================================================
// K1: fold nc_w/nc_b into combined kv/ctxp weight
// ========================================================================
__global__ void prep_kernel(const float* __restrict__ nc_w,
                            const float* __restrict__ nc_b,
                            const float* __restrict__ wkv,
                            const float* __restrict__ bkv,
                            const float* __restrict__ wcf,
                            const float* __restrict__ bcf) {
    int j = blockIdx.x * blockDim.x + threadIdx.x;
    if (j >= KVP) return;
    if (j < 512) {
        int l  = j >> 8;
        int jj = j & 255;
        const float* w = wkv + (size_t)l * DI * 256;
        float bias = bkv[l*256 + jj];
        for (int c = 0; c < DI; c++) {
            float wv = w[c*256 + jj];
            g_W[c*KVP + j] = nc_w[l*DI + c] * wv;
            bias += nc_b[l*DI + c] * wv;
        }
        g_bias[j] = bias;
    } else {
        int jj = j - 512;
        for (int c = 0; c < DI; c++)
            g_W[c*KVP + j] = wcf[c*DI + jj];
        g_bias[j] = bcf[jj];
    }
}

// ========================================================================
// K1b: fp16(hi) weight tiles, [k][n] stride 136
// ========================================================================
__global__ void prepw_kernel(const float* __restrict__ wq,
                             const float* __restrict__ wo,
                             const float* __restrict__ w1,
                             const float* __restrict__ w2,
                             const float* __restrict__ wqf) {
    int tile = blockIdx.x;
    for (int idx = threadIdx.x; idx < DI*DI; idx += blockDim.x) {
        int k = idx >> 7, n = idx & 127;
        float w;
        if (tile >= 21)      w = g_W[k*KVP + (tile-21)*128 + n];
        else if (tile == 20) w = wqf[k*DI + n];
        else {
            int l = tile / 10, s = tile % 10;
            if (s == 0)      w = wq[l*DI*DI + k*DI + n];
            else if (s == 1) w = wo[l*DI*DI + k*DI + n];
            else if (s < 6)  w = w1[l*DI*512 + k*512 + (s-2)*128 + n];
            else             w = w2[l*512*DI + ((s-6)*128 + k)*DI + n];
        }
        g_Whi[(size_t)tile*WTS + k*136 + n] = __float2half_rn(w);
    }
}

// ========================================================================
// K2: transpose feat_map + fused LayerNorm (coalesced writes)
// ========================================================================
__global__ void trln_kernel(const float* __restrict__ fm) {
    __shared__ float st[DI][33];
    __shared__ float mu_s[32], rs_s[32];
    int dp0 = blockIdx.x * 32;
    int b = dp0 / SDL, hw0 = dp0 % SDL;
    const float* src = fm + (size_t)b * DI * SDL + hw0;
    int t = threadIdx.x;
    #pragma unroll
    for (int i = 0; i < 16; i++) {
        int e = t + i*256;
        int c = e >> 5, p = e & 31;
        st[c][p] = src[(size_t)c*SDL + p];
    }
    __syncthreads();
    int p = t >> 3, g = t & 7;
    float s = 0.f, s2 = 0.f;
    #pragma unroll
    for (int i = 0; i < 16; i++) {
        float v = st[g*16 + i][p];
        s += v; s2 += v*v;
    }
    #pragma unroll
    for (int off = 4; off; off >>= 1) {
        s  += __shfl_xor_sync(0xffffffffu, s,  off, 8);
        s2 += __shfl_xor_sync(0xffffffffu, s2, off, 8);
    }
    if (g == 0) {
        float mu = s * (1.f/128.f);
        mu_s[p] = mu;
        rs_s[p] = rsqrtf(s2*(1.f/128.f) - mu*mu + 1e-6f);
    }
    __syncthreads();
    #pragma unroll
    for (int i = 0; i < 16; i++) {
        int f = t + i*256;
        int r = f >> 7, c = f & 127;
        g_ctxln[(size_t)(dp0 + r)*DI + c] = (st[c][r] - mu_s[r]) * rs_s[r];
    }
}

// ========================================================================
// K3: transpose feat_map_up -> x rows (coalesced writes)
// ========================================================================
__global__ void trx_kernel(const float* __restrict__ fmu) {
    __shared__ float st[DI][33];
    int n0 = blockIdx.x * 32;
    int b = n0 / SPL, s0 = n0 % SPL;
    const float* src = fmu + (size_t)b * DI * SPL + s0;
    int t = threadIdx.x;
    #pragma unroll
    for (int i = 0; i < 16; i++) {
        int e = t + i*256;
        int c = e >> 5, p = e & 31;
        st[c][p] = src[(size_t)c*SPL + p];
    }
    __syncthreads();
    #pragma unroll
    for (int i = 0; i < 16; i++) {
        int f = t + i*256;
        int r = f >> 7, c = f & 127;
        g_x[(size_t)(n0 + r)*DI + c] = st[c][r];
    }
}

// ========================================================================
// K4: per-dpixel GEMM  g_kvp = g_ctxln @ g_W + g_bias  (split-A 2-term)
// SMEM: sAhi 4352 | sAlo 4352 | sBhi 4352 = 13056 floats, 2 CTAs/SM
// ========================================================================
#define DGEMM_SMEM (13056*4)
__global__ void __launch_bounds__(256, 2) dgemm_kernel() {
    extern __shared__ __align__(16) float smf[];
    char* sAhi = (char*)(smf);
    char* sAlo = (char*)(smf + 4352);
    char* sBhi = (char*)(smf + 8704);
    const int t = threadIdx.x, lane = t & 31, w = t >> 5;
    const int gid = lane >> 2, tid = lane & 3;
    const int mrow = (w & 3) * 16;
    const int nh   = w >> 2;
    const int r0f = mrow + gid, r1f = r0f + 8;
    const int n0 = blockIdx.x * 64;

    PF pf;
    pf_load<256>(pf, 21, 0, t);
    for (int f = t; f < 4096; f += 256) {
        int r = f >> 6, c2 = f & 63;
        const float* src = g_ctxln + (size_t)(n0 + r)*DI + 2*c2;
        w2a(sAhi, sAlo, r, 2*c2, src[0], src[1]);
    }
    __syncthreads();

    float acc[8][4];
    for (int i = 0; i < 5; i++) {
        #pragma unroll
        for (int nt = 0; nt < 8; nt++) { acc[nt][0]=acc[nt][1]=acc[nt][2]=acc[nt][3]=0.f; }
        gemm_tile_pf(pf, sAhi, sAlo, sBhi, acc, 21 + i,
                     (i < 4) ? 22 + i : -1, mrow, nh, lane, t);
        #pragma unroll
        for (int nt = 0; nt < 8; nt++) {
            int c = nh*64 + 8*nt + 2*tid;
            float2 b = *(const float2*)(g_bias + i*128 + c);
            *(float2*)(g_kvp + (size_t)(n0+r0f)*KVP + i*128 + c) =
                make_float2(acc[nt][0]+b.x, acc[nt][1]+b.y);
            *(float2*)(g_kvp + (size_t)(n0+r1f)*KVP + i*128 + c) =
                make_float2(acc[nt][2]+b.x, acc[nt][3]+b.y);
        }
    }
}

// ========================================================================
// K5: HMMA mega kernel — 128 pixels/block, 512 threads, 1 CTA/SM
// SMEM float offsets (A tile = 128x136 fp16 = 8704 floats):
//   0      sAhi   8704      (probs[9][132] aliases in tail)
//   8704   sAg    8704      (gelu output A tile)
//   17408  sB0    4352      qbuf[128][132]=16896 aliases 8704..25600
//   21760  sB1    4352
//   26112  xf [128][132]    16896
// total 43008 floats = 172032 B  -> 1 CTA/SM
// ========================================================================
#define MEGA_SMEM (43008*4)

__device__ __forceinline__ float gelu_tanh(float v) {
    float u = 0.7978845608028654f * (v + 0.044715f * v * v * v);
    u = fminf(fmaxf(u, -15.f), 15.f);
    float e = __expf(-2.f * u);
    float th = (1.f - e) / (1.f + e);
    return 0.5f * v * (1.f + th);
}

__device__ __forceinline__ void calc_dpix(int n, int dpix[9]) {
    int b  = n / SPL, s = n % SPL;
    int hu = s / WUm, wu = s % WUm;
    int hd = hu >> 1, wd = wu >> 1;
    #pragma unroll
    for (int i = 0; i < 3; i++)
        #pragma unroll
        for (int j = 0; j < 3; j++) {
            int hs = min(max(hd - 1 + i, 0), HDm - 1);
            int ws = min(max(wd - 1 + j, 0), WDm - 1);
            dpix[i*3 + j] = b*SDL + hs*WDm + ws;
        }
}

// LayerNorm: 4 lanes per row (shfl reduce), write fp16 A tile (hi only)
__device__ __forceinline__ void ln_writeA(const float* xf,
                                          char* Ahi, int rr, int c4) {
    const float* xr = xf + rr*132 + c4*32;
    float s = 0.f, s2 = 0.f;
    #pragma unroll
    for (int i = 0; i < 8; i++) {
        float4 v = *(const float4*)(xr + i*4);
        s  += (v.x + v.y) + (v.z + v.w);
        s2 += (v.x*v.x + v.y*v.y) + (v.z*v.z + v.w*v.w);
    }
    s  += __shfl_xor_sync(0xffffffffu, s, 1, 4);
    s  += __shfl_xor_sync(0xffffffffu, s, 2, 4);
    s2 += __shfl_xor_sync(0xffffffffu, s2, 1, 4);
    s2 += __shfl_xor_sync(0xffffffffu, s2, 2, 4);
    float mu   = s * (1.f/128.f);
    float rstd = rsqrtf(s2*(1.f/128.f) - mu*mu + 1e-6f);
    #pragma unroll
    for (int j = 0; j < 32; j += 2) {
        float v0 = (xr[j]   - mu) * rstd;
        float v1 = (xr[j+1] - mu) * rstd;
        w2a_hi(Ahi, rr, c4*32 + j, v0, v1);
    }
}

#define ZACC() do { _Pragma("unroll") \
    for (int _i = 0; _i < 8; _i++) { acc[_i][0]=acc[_i][1]=acc[_i][2]=acc[_i][3]=0.f; } } while(0)

__global__ void __launch_bounds__(512, 1) mega_kernel(
    const float* __restrict__ bq,  const float* __restrict__ bo,
    const float* __restrict__ b1,  const float* __restrict__ b2,
    const float* __restrict__ bqf, float* __restrict__ out)
{
    extern __shared__ __align__(16) float smf[];
    char*  sAhi = (char*)(smf);
    char*  sAg  = (char*)(smf + 8704);
    char*  sB0  = (char*)(smf + 17408);
    char*  sB1  = (char*)(smf + 21760);
    float* qbuf = smf + 8704;            // aliases sAg+sB0+sB1 (sequenced)
    float* xf   = smf + 26112;           // 128 x 132

    const int t    = threadIdx.x;
    const int lane = t & 31;
    const int w    = t >> 5;              // 0..15
    const int gid  = lane >> 2, tid = lane & 3;
    const int mrow = (w & 7) * 16;        // 8 warp row blocks
    const int nh   = w >> 3;              // 2 col halves
    const int r0f  = mrow + gid;
    const int r1f  = r0f + 8;
    const int rr   = t >> 2;              // pixel row (LN) 0..127
    const int c4   = t & 3;               // col chunk (LN)
    const int j8   = lane >> 3;           // gather group in warp
    const int l8   = lane & 7;            // lane in gather group
    const int n0   = blockIdx.x * 128;

    float acc[8][4];
    PF pf;
    pf_load<512>(pf, 0, 0, t);            // prefetch wq[l=0] half0

    // load x into xf (stride 132)
    {
        const float* src = g_x + (size_t)(n0 + rr)*DI + c4*32;
        float* dst = xf + rr*132 + c4*32;
        #pragma unroll
        for (int i = 0; i < 8; i++)
            *(float4*)(dst + i*4) = *(const float4*)(src + i*4);
    }
    __syncthreads();

    for (int l = 0; l < 2; l++) {
        int tb = l*10;

        // ===== q = LN(x) @ wq (bias added in attention) =====
        ln_writeA(xf, sAhi, rr, c4);
        ZACC();
        gemm_tile_db1(pf, sAhi, sB0, sB1, acc, tb + 0, tb + 1,
                      mrow, nh, lane, t);
        __syncthreads();                       // all mma reads done
        #pragma unroll
        for (int nt = 0; nt < 8; nt++) {       // frag -> qbuf
            int c = nh*64 + 8*nt + 2*tid;
            *(float2*)(qbuf + r0f*132 + c) = make_float2(acc[nt][0], acc[nt][1]);
            *(float2*)(qbuf + r1f*132 + c) = make_float2(acc[nt][2], acc[nt][3]);
        }
        __syncthreads();

        // ===== attention: 8-lane cooperative gathers, 8 rounds =====
        for (int ro = 0; ro < 8; ro++) {
            int g = ro*64 + w*4 + j8;          // pixel-head 0..511
            int p = g >> 2, h = g & 3;
            int dpix[9];
            calc_dpix(n0 + p, dpix);
            float4 qv = *(const float4*)(qbuf + p*132 + h*32 + l8*4);
            float4 bv = *(const float4*)(bq + l*DI + h*32 + l8*4);
            float q0 = qv.x + bv.x, q1 = qv.y + bv.y;
            float q2 = qv.z + bv.z, q3 = qv.w + bv.w;
            float lo[9];
            float m = -1e30f;
            #pragma unroll
            for (int kk = 0; kk < 9; kk++) {
                const float* kv = g_kvp + (size_t)dpix[kk]*KVP + l*256
                                  + h*32 + l8*4;
                float4 k4 = __ldg((const float4*)kv);
                float d = q0*k4.x + q1*k4.y + q2*k4.z + q3*k4.w;
                d += __shfl_xor_sync(0xffffffffu, d, 1, 8);
                d += __shfl_xor_sync(0xffffffffu, d, 2, 8);
                d += __shfl_xor_sync(0xffffffffu, d, 4, 8);
                lo[kk] = d * 0.17677669529663687f;
                m = fmaxf(m, lo[kk]);
            }
            float ssum = 0.f;
            #pragma unroll
            for (int kk = 0; kk < 9; kk++) {
                lo[kk] = __expf(lo[kk] - m);
                ssum += lo[kk];
            }
            float inv = 1.f / ssum;
            float o0 = 0.f, o1 = 0.f, o2 = 0.f, o3 = 0.f;
            #pragma unroll
            for (int kk = 0; kk < 9; kk++) {
                float wgt = lo[kk] * inv;
                const float* vv = g_kvp + (size_t)dpix[kk]*KVP + l*256 + 128
                                  + h*32 + l8*4;
                float4 v = __ldg((const float4*)vv);
                o0 += wgt*v.x; o1 += wgt*v.y; o2 += wgt*v.z; o3 += wgt*v.w;
            }
            w2a_hi(sAhi, p, h*32 + l8*4,     o0, o1);
            w2a_hi(sAhi, p, h*32 + l8*4 + 2, o2, o3);
        }
        __syncthreads();                     // qbuf reads + sAhi writes done

        // ===== x += o @ wo + bo =====
        ZACC();
        gemm_tile_db1(pf, sAhi, sB0, sB1, acc, tb + 1, tb + 2,
                      mrow, nh, lane, t);
        #pragma unroll
        for (int nt = 0; nt < 8; nt++) {     // xf-only epilogue
            int c = nh*64 + 8*nt + 2*tid;
            float2 b = *(const float2*)(bo + l*DI + c);
            float2* p0 = (float2*)(xf + r0f*132 + c);
            float2* p1 = (float2*)(xf + r1f*132 + c);
            float2 v0 = *p0, v1 = *p1;
            v0.x += acc[nt][0] + b.x; v0.y += acc[nt][1] + b.y;
            v1.x += acc[nt][2] + b.x; v1.y += acc[nt][3] + b.y;
            *p0 = v0; *p1 = v1;
        }
        __syncthreads();                     // xf ready for LN

        // ===== MLP: LN once; w1 reads sAhi, gelu -> sAg, w2 reads sAg =====
        ln_writeA(xf, sAhi, rr, c4);
        for (int hc = 0; hc < 4; hc++) {
            ZACC();
            gemm_tile_db1(pf, sAhi, sB0, sB1, acc, tb + 2 + hc,
                          tb + 6 + hc, mrow, nh, lane, t);
            #pragma unroll
            for (int nt = 0; nt < 8; nt++) {    // gelu -> sAg
                int c = nh*64 + 8*nt + 2*tid;
                float2 b = *(const float2*)(b1 + l*512 + hc*128 + c);
                w2a_hi(sAg, r0f, c,
                       gelu_tanh(acc[nt][0] + b.x), gelu_tanh(acc[nt][1] + b.y));
                w2a_hi(sAg, r1f, c,
                       gelu_tanh(acc[nt][2] + b.x), gelu_tanh(acc[nt][3] + b.y));
            }
            int nxt = (hc < 3) ? (tb + 3 + hc) : ((l == 0) ? 10 : 20);
            ZACC();
            gemm_tile_db1(pf, sAg, sB0, sB1, acc, tb + 6 + hc,
                          nxt, mrow, nh, lane, t);
            #pragma unroll
            for (int nt = 0; nt < 8; nt++) {    // += into xf (+b2 on last)
                int c = nh*64 + 8*nt + 2*tid;
                float2 b = (hc == 3) ? *(const float2*)(b2 + l*DI + c)
                                     : make_float2(0.f, 0.f);
                float2* p0 = (float2*)(xf + r0f*132 + c);
                float2* p1 = (float2*)(xf + r1f*132 + c);
                float2 v0 = *p0, v1 = *p1;
                v0.x += acc[nt][0] + b.x; v0.y += acc[nt][1] + b.y;
                v1.x += acc[nt][2] + b.x; v1.y += acc[nt][3] + b.y;
                *p0 = v0; *p1 = v1;
            }
        }
        __syncthreads();                     // xf complete for next LN
    }

    // ===== final: xq = LN(x) @ wqf + bqf -> qbuf =====
    ln_writeA(xf, sAhi, rr, c4);
    ZACC();
    gemm_tile_db1(pf, sAhi, sB0, sB1, acc, 20, -1, mrow, nh, lane, t);
    __syncthreads();                         // mma done -> qbuf writable
    #pragma unroll
    for (int nt = 0; nt < 8; nt++) {
        int c = nh*64 + 8*nt + 2*tid;
        float2 b = *(const float2*)(bqf + c);
        *(float2*)(qbuf + r0f*132 + c) = make_float2(acc[nt][0]+b.x, acc[nt][1]+b.y);
        *(float2*)(qbuf + r1f*132 + c) = make_float2(acc[nt][2]+b.x, acc[nt][3]+b.y);
    }
    __syncthreads();

    // ===== logits + 9-way softmax: warp w round ro -> pixel ro*16+w =====
    {
        float* probs = smf;                  // reuse sAhi region, [kk][132]
        for (int ro = 0; ro < 8; ro++) {
            int p = ro*16 + w;
            int dpix[9];
            calc_dpix(n0 + p, dpix);
            int cidx = j8*32 + l8*4;
            float4 xv = *(const float4*)(qbuf + p*132 + cidx);
            float lo[9];
            #pragma unroll
            for (int kk = 0; kk < 9; kk++) {
                const float* cp = g_kvp + (size_t)dpix[kk]*KVP + 512 + cidx;
                float4 c4v = __ldg((const float4*)cp);
                float d = xv.x*c4v.x + xv.y*c4v.y + xv.z*c4v.z + xv.w*c4v.w;
                d += __shfl_xor_sync(0xffffffffu, d, 1);
                d += __shfl_xor_sync(0xffffffffu, d, 2);
                d += __shfl_xor_sync(0xffffffffu, d, 4);
                d += __shfl_xor_sync(0xffffffffu, d, 8);
                d += __shfl_xor_sync(0xffffffffu, d, 16);
                lo[kk] = d * 0.08838834764831845f;
            }
            float m = -1e30f;
            #pragma unroll
            for (int kk = 0; kk < 9; kk++) m = fmaxf(m, lo[kk]);
            float ssum = 0.f;
            #pragma unroll
            for (int kk = 0; kk < 9; kk++) {
                lo[kk] = __expf(lo[kk] - m);
                ssum += lo[kk];
            }
            float inv = 1.f / ssum;
            if (lane == 0) {
                #pragma unroll
                for (int kk = 0; kk < 9; kk++)
                    probs[kk*132 + p] = lo[kk] * inv;
            }
        }
        __syncthreads();
        int b = n0 / SPL, s0 = n0 % SPL;
        for (int f = t; f < 9*128; f += 512) {
            int kk = f >> 7, p = f & 127;
            out[(size_t)b*9*SPL + (size_t)kk*SPL + s0 + p] = probs[kk*132 + p];
        }
    }
}

// ========================================================================
extern "C" void kernel_launch(void* const* d_in, const int* in_sizes, int n_in,
                              void* d_out, int out_size) {
    const float* feat_map    = (const float*)d_in[0];
    const float* feat_map_up = (const float*)d_in[1];
    const float* nc_w = (const float*)d_in[2];
    const float* nc_b = (const float*)d_in[3];
    const float* wq   = (const float*)d_in[4];
    const float* bq   = (const float*)d_in[5];
    const float* wkv  = (const float*)d_in[6];
    const float* bkv  = (const float*)d_in[7];
    const float* wo   = (const float*)d_in[8];
    const float* bo   = (const float*)d_in[9];
    const float* w1   = (const float*)d_in[10];
    const float* b1   = (const float*)d_in[11];
    const float* w2   = (const float*)d_in[12];
    const float* b2   = (const float*)d_in[13];
    const float* wqf  = (const float*)d_in[14];
    const float* bqf  = (const float*)d_in[15];
    const float* wcf  = (const float*)d_in[16];
    const float* bcf  = (const float*)d_in[17];
    float* out = (float*)d_out;

    cudaFuncSetAttribute(dgemm_kernel,
                         cudaFuncAttributeMaxDynamicSharedMemorySize, DGEMM_SMEM);
    cudaFuncSetAttribute(mega_kernel,
                         cudaFuncAttributeMaxDynamicSharedMemorySize, MEGA_SMEM);

    prep_kernel<<<3, 256>>>(nc_w, nc_b, wkv, bkv, wcf, bcf);
    prepw_kernel<<<NTILES, 256>>>(wq, wo, w1, w2, wqf);
    trln_kernel<<<ND/32, 256>>>(feat_map);
    trx_kernel<<<NP/32, 256>>>(feat_map_up);
    dgemm_kernel<<<ND/64, 256, DGEMM_SMEM>>>();
    mega_kernel<<<NP/128, 512, MEGA_SMEM>>>(bq, bo, b1, b2, bqf, out);
}